// round 1
// baseline (speedup 1.0000x reference)
#include <cuda_runtime.h>
#include <cuda_bf16.h>
#include <math_constants.h>

// Problem constants
#define BATCH 2
#define SEQ   2048
#define CH    1024
#define HEADS 16
#define DH    64
#define MROWS (BATCH*SEQ)   // 4096

// Scratch (device globals — no allocation allowed in kernel_launch)
__device__ float g_qkv[(size_t)MROWS * 3 * CH];  // [B*T, 3*C]  ~50 MB
__device__ float g_att[(size_t)MROWS * CH];      // [B*T, C]    ~17 MB

// ---------------------------------------------------------------------------
// Register-blocked SGEMM: C[M,N] = A[M,K] @ B[K,N] + bias[N]
// BM=128, BN=128, BK=16, thread tile 8x8, 256 threads.
// Assumes M%128==0, N%128==0, K%16==0 (true for both GEMMs here).
// ---------------------------------------------------------------------------
__global__ __launch_bounds__(256, 2)
void sgemm_bias_kernel(const float* __restrict__ A,
                       const float* __restrict__ B,
                       const float* __restrict__ bias,
                       float* __restrict__ C,
                       int M, int N, int K)
{
    constexpr int BM = 128, BN = 128, BK = 16, TM = 8, TN = 8;
    __shared__ float As[BK][BM];   // A transposed in smem
    __shared__ float Bs[BK][BN];

    const int tid = threadIdx.x;
    const int bx = blockIdx.x;     // N tile
    const int by = blockIdx.y;     // M tile

    const int tx = tid % (BN / TN);   // 0..15
    const int ty = tid / (BN / TN);   // 0..15

    // A tile load mapping: 128x16 floats = 512 float4; 256 threads x 2
    const int aRow  = tid >> 2;       // 0..63
    const int aCol4 = tid & 3;        // 0..3  (float4 index within BK)
    // B tile load mapping: 16x128 floats = 512 float4; 256 threads x 2
    const int bRow  = tid >> 5;       // 0..7
    const int bCol4 = tid & 31;       // 0..31

    const float* Aptr = A + (size_t)by * BM * K;
    const float* Bptr = B + (size_t)bx * BN;

    float acc[TM][TN];
    #pragma unroll
    for (int i = 0; i < TM; i++)
        #pragma unroll
        for (int j = 0; j < TN; j++) acc[i][j] = 0.0f;

    for (int k0 = 0; k0 < K; k0 += BK) {
        // load A tile (transpose into As)
        #pragma unroll
        for (int it = 0; it < 2; it++) {
            int r = aRow + it * 64;
            float4 v = *(const float4*)(Aptr + (size_t)r * K + k0 + aCol4 * 4);
            As[aCol4 * 4 + 0][r] = v.x;
            As[aCol4 * 4 + 1][r] = v.y;
            As[aCol4 * 4 + 2][r] = v.z;
            As[aCol4 * 4 + 3][r] = v.w;
        }
        // load B tile
        #pragma unroll
        for (int it = 0; it < 2; it++) {
            int r = bRow + it * 8;
            float4 v = *(const float4*)(Bptr + (size_t)(k0 + r) * N + bCol4 * 4);
            *(float4*)&Bs[r][bCol4 * 4] = v;
        }
        __syncthreads();

        #pragma unroll
        for (int kk = 0; kk < BK; kk++) {
            float ra[TM], rb[TN];
            #pragma unroll
            for (int i = 0; i < TM; i += 4)
                *(float4*)&ra[i] = *(const float4*)&As[kk][ty * TM + i];
            #pragma unroll
            for (int j = 0; j < TN; j += 4)
                *(float4*)&rb[j] = *(const float4*)&Bs[kk][tx * TN + j];
            #pragma unroll
            for (int i = 0; i < TM; i++)
                #pragma unroll
                for (int j = 0; j < TN; j++)
                    acc[i][j] = fmaf(ra[i], rb[j], acc[i][j]);
        }
        __syncthreads();
    }

    // epilogue: bias + store
    #pragma unroll
    for (int i = 0; i < TM; i++) {
        int row = by * BM + ty * TM + i;
        #pragma unroll
        for (int j = 0; j < TN; j += 4) {
            int col = bx * BN + tx * TN + j;
            float4 bv = *(const float4*)(bias + col);
            float4 o;
            o.x = acc[i][j + 0] + bv.x;
            o.y = acc[i][j + 1] + bv.y;
            o.z = acc[i][j + 2] + bv.z;
            o.w = acc[i][j + 3] + bv.w;
            *(float4*)(C + (size_t)row * N + col) = o;
        }
    }
}

// ---------------------------------------------------------------------------
// Fenwick sparse attention.
// Mask row t (causal): {t} ∪ {t-1, t-2, t-4, ..., t-2^k >= 0}  → ≤12 entries.
// One warp per (b, h, t); each lane owns dims {lane, lane+32} of Dh=64.
// qkv layout per (b,t) row: [3][H][Dh] contiguous (stride 3*C).
// out: [B*T, C] with head h at offset h*Dh.
// ---------------------------------------------------------------------------
__global__ __launch_bounds__(256)
void fenwick_attn_kernel(const float* __restrict__ qkv, float* __restrict__ out)
{
    const int warp = threadIdx.x >> 5;
    const int lane = threadIdx.x & 31;
    const int t  = blockIdx.x * 8 + warp;
    const int bh = blockIdx.y;
    const int b = bh >> 4;        // / HEADS
    const int h = bh & 15;        // % HEADS

    const float scale = 0.125f;   // 64^-0.5
    const size_t rowStride = 3 * CH;
    const float* base = qkv + (size_t)b * SEQ * rowStride;

    // query
    const float* qp = base + (size_t)t * rowStride + 0 * CH + h * DH;
    const float q0 = qp[lane];
    const float q1 = qp[lane + 32];

    // Fenwick positions
    int pos[12];
    int np = 0;
    pos[np++] = t;
    for (int step = 1; t - step >= 0; step <<= 1) pos[np++] = t - step;

    // scores
    float s[12];
    float m = -CUDART_INF_F;
    for (int i = 0; i < np; i++) {
        const float* kp = base + (size_t)pos[i] * rowStride + CH + h * DH;
        float d = q0 * kp[lane] + q1 * kp[lane + 32];
        #pragma unroll
        for (int off = 16; off; off >>= 1) d += __shfl_xor_sync(0xFFFFFFFFu, d, off);
        d *= scale;
        s[i] = d;
        m = fmaxf(m, d);
    }

    float denom = 0.0f;
    for (int i = 0; i < np; i++) { s[i] = __expf(s[i] - m); denom += s[i]; }
    const float inv = 1.0f / denom;

    float o0 = 0.0f, o1 = 0.0f;
    for (int i = 0; i < np; i++) {
        const float* vp = base + (size_t)pos[i] * rowStride + 2 * CH + h * DH;
        o0 = fmaf(s[i], vp[lane], o0);
        o1 = fmaf(s[i], vp[lane + 32], o1);
    }

    float* op = out + ((size_t)b * SEQ + t) * CH + h * DH;
    op[lane]      = o0 * inv;
    op[lane + 32] = o1 * inv;
}

// ---------------------------------------------------------------------------
// Launch: qkv GEMM -> sparse attention -> proj GEMM (sequential, one stream)
// ---------------------------------------------------------------------------
extern "C" void kernel_launch(void* const* d_in, const int* in_sizes, int n_in,
                              void* d_out, int out_size)
{
    const float* x      = (const float*)d_in[0];  // [B,T,C]
    const float* W_qkv  = (const float*)d_in[1];  // [C, 3C]
    const float* b_qkv  = (const float*)d_in[2];  // [3C]
    const float* W_proj = (const float*)d_in[3];  // [C, C]
    const float* b_proj = (const float*)d_in[4];  // [C]
    float* out = (float*)d_out;                   // [B,T,C]

    float* qkv;
    float* att;
    cudaGetSymbolAddress((void**)&qkv, g_qkv);
    cudaGetSymbolAddress((void**)&att, g_att);

    // GEMM 1: [4096,1024] @ [1024,3072] + b_qkv
    {
        dim3 grid(3 * CH / 128, MROWS / 128);
        sgemm_bias_kernel<<<grid, 256>>>(x, W_qkv, b_qkv, qkv, MROWS, 3 * CH, CH);
    }
    // Sparse Fenwick attention
    {
        dim3 grid(SEQ / 8, BATCH * HEADS);
        fenwick_attn_kernel<<<grid, 256>>>(qkv, att);
    }
    // GEMM 3: [4096,1024] @ [1024,1024] + b_proj
    {
        dim3 grid(CH / 128, MROWS / 128);
        sgemm_bias_kernel<<<grid, 256>>>(att, W_proj, b_proj, out, MROWS, CH, CH);
    }
}

// round 3
// speedup vs baseline: 3.9911x; 3.9911x over previous
#include <cuda_runtime.h>
#include <cuda_bf16.h>
#include <math_constants.h>
#include <cstdint>

// Problem constants
#define BATCH 2
#define SEQ   2048
#define CH    1024
#define HEADS 16
#define DH    64
#define MROWS (BATCH*SEQ)   // 4096

// Detect family-specific sm_103a compilation (tcgen05 available)
#if defined(__CUDA_ARCH_FEAT_SM103_ALL) || defined(__CUDA_ARCH_FEAT_SM100_ALL)
#define USE_TCGEN05 1
#else
#define USE_TCGEN05 0
#endif

// ---------------------------------------------------------------------------
// Device scratch
// ---------------------------------------------------------------------------
__device__ float g_qkv[(size_t)MROWS * 3 * CH];
__device__ float g_att[(size_t)MROWS * CH];
__device__ __nv_bfloat16 g_Ahi[(size_t)MROWS * CH];
__device__ __nv_bfloat16 g_Alo[(size_t)MROWS * CH];
__device__ __nv_bfloat16 g_BQhi[(size_t)(3*CH) * CH];
__device__ __nv_bfloat16 g_BQlo[(size_t)(3*CH) * CH];
__device__ __nv_bfloat16 g_BPhi[(size_t)CH * CH];
__device__ __nv_bfloat16 g_BPlo[(size_t)CH * CH];

// ---------------------------------------------------------------------------
// Common helpers
// ---------------------------------------------------------------------------
__device__ __forceinline__ uint32_t smem_u32(const void* p) {
    uint32_t a;
    asm("{ .reg .u64 t; cvta.to.shared.u64 t, %1; cvt.u32.u64 %0, t; }"
        : "=r"(a) : "l"(p));
    return a;
}

#define SWZ128(o) ((o) ^ (((o) >> 3) & 0x70))

#define CP_ASYNC16(dst_u32, src_ptr) \
    asm volatile("cp.async.cg.shared.global [%0], [%1], 16;\n" \
                 :: "r"(dst_u32), "l"(src_ptr))
#define CP_COMMIT() asm volatile("cp.async.commit_group;\n" ::: "memory")
#define CP_WAIT0()  asm volatile("cp.async.wait_group 0;\n" ::: "memory")
#define CP_WAIT1()  asm volatile("cp.async.wait_group 1;\n" ::: "memory")

#define MBARRIER_INIT(addr, cnt) \
    asm volatile("mbarrier.init.shared.b64 [%0], %1;" :: "r"(addr), "r"(cnt) : "memory")

#define MBARRIER_WAIT_PARITY(addr, parity) do { \
    uint32_t _m = (addr); uint32_t _p = (parity); uint32_t _d; \
    asm volatile("{\n\t.reg .pred p;\n\t" \
        "mbarrier.try_wait.parity.acquire.cta.shared::cta.b64 p, [%1], %2;\n\t" \
        "selp.b32 %0, 1, 0, p;\n\t}" : "=r"(_d) : "r"(_m), "r"(_p) : "memory"); \
    if (!_d) { \
        asm volatile("{\n\t.reg .pred P1;\n\t" \
            "WL_%=:\n\t" \
            "mbarrier.try_wait.parity.acquire.cta.shared::cta.b64 P1, [%0], %1, 0x989680;\n\t" \
            "@P1 bra.uni WD_%=;\n\t" \
            "bra.uni WL_%=;\n\t" \
            "WD_%=:\n\t}" :: "r"(_m), "r"(_p) : "memory"); \
    } \
} while (0)

#define FENCE_PROXY_ASYNC() \
    asm volatile("fence.proxy.async.shared::cta;" ::: "memory")

// ---------------------------------------------------------------------------
// tcgen05 helpers (only instantiated when USE_TCGEN05)
// ---------------------------------------------------------------------------
#if USE_TCGEN05
#define TCGEN05_ALLOC(smem_addr, ncols) \
    asm volatile("tcgen05.alloc.cta_group::1.sync.aligned.shared::cta.b32 [%0], %1;" \
                 :: "r"(smem_addr), "r"(ncols) : "memory")
#define TCGEN05_DEALLOC(tmem, ncols) \
    asm volatile("tcgen05.dealloc.cta_group::1.sync.aligned.b32 %0, %1;" \
                 :: "r"(tmem), "r"(ncols))
#define TCGEN05_RELINQ() \
    asm volatile("tcgen05.relinquish_alloc_permit.cta_group::1.sync.aligned;")
#define TCGEN05_COMMIT(mbar) \
    asm volatile("tcgen05.commit.cta_group::1.mbarrier::arrive::one.shared::cluster.b64 [%0];" \
                 :: "r"(mbar) : "memory")
#define TCGEN05_FENCE_AFTER() \
    asm volatile("tcgen05.fence::after_thread_sync;" ::: "memory")
#define TCGEN05_FENCE_BEFORE() \
    asm volatile("tcgen05.fence::before_thread_sync;" ::: "memory")
#define TCGEN05_WAIT_LD() \
    asm volatile("tcgen05.wait::ld.sync.aligned;" ::: "memory")

__device__ __forceinline__ void mma_bf16_ss(uint32_t d_tmem, uint64_t a_desc,
                                            uint64_t b_desc, uint32_t idesc,
                                            uint32_t enable_d) {
    asm volatile(
        "{\n\t"
        ".reg .pred p;\n\t"
        "setp.ne.u32 p, %5, 0;\n\t"
        "tcgen05.mma.cta_group::1.kind::f16 [%0], %1, %2, %3, {%4, %4, %4, %4}, p;\n\t"
        "}"
        :: "r"(d_tmem), "l"(a_desc), "l"(b_desc), "r"(idesc), "r"(0u), "r"(enable_d)
        : "memory");
}

#define LDTM_X32(r, addr) \
    asm volatile( \
        "tcgen05.ld.sync.aligned.32x32b.x32.b32 " \
        "{%0, %1, %2, %3, %4, %5, %6, %7, " \
        " %8, %9, %10, %11, %12, %13, %14, %15, " \
        " %16, %17, %18, %19, %20, %21, %22, %23, " \
        " %24, %25, %26, %27, %28, %29, %30, %31}, [%32];" \
        : "=r"((r)[0]),  "=r"((r)[1]),  "=r"((r)[2]),  "=r"((r)[3]), \
          "=r"((r)[4]),  "=r"((r)[5]),  "=r"((r)[6]),  "=r"((r)[7]), \
          "=r"((r)[8]),  "=r"((r)[9]),  "=r"((r)[10]), "=r"((r)[11]), \
          "=r"((r)[12]), "=r"((r)[13]), "=r"((r)[14]), "=r"((r)[15]), \
          "=r"((r)[16]), "=r"((r)[17]), "=r"((r)[18]), "=r"((r)[19]), \
          "=r"((r)[20]), "=r"((r)[21]), "=r"((r)[22]), "=r"((r)[23]), \
          "=r"((r)[24]), "=r"((r)[25]), "=r"((r)[26]), "=r"((r)[27]), \
          "=r"((r)[28]), "=r"((r)[29]), "=r"((r)[30]), "=r"((r)[31]) \
        : "r"(addr))

static __device__ __forceinline__ uint64_t make_desc(uint32_t base_addr) {
    const uint64_t DESC_BASE =
        (uint64_t(2)  << 61) | (uint64_t(1) << 46) |
        (uint64_t(64) << 32) | (uint64_t(1) << 16);
    return DESC_BASE | ((uint64_t)(base_addr >> 4) & 0x3FFF);
}

#define IDESC_BF16_128x128 0x08200490u
#endif  // USE_TCGEN05

// ---------------------------------------------------------------------------
// mma.sync helpers (fallback path, valid on any sm_80+)
// ---------------------------------------------------------------------------
#define LDSM_X4(r0, r1, r2, r3, addr) \
    asm volatile("ldmatrix.sync.aligned.m8n8.x4.shared.b16 {%0,%1,%2,%3}, [%4];" \
                 : "=r"(r0), "=r"(r1), "=r"(r2), "=r"(r3) : "r"(addr))
#define LDSM_X2(r0, r1, addr) \
    asm volatile("ldmatrix.sync.aligned.m8n8.x2.shared.b16 {%0,%1}, [%2];" \
                 : "=r"(r0), "=r"(r1) : "r"(addr))
#define MMA16816(d, a0, a1, a2, a3, b0, b1) \
    asm volatile("mma.sync.aligned.m16n8k16.row.col.f32.bf16.bf16.f32 " \
                 "{%0,%1,%2,%3},{%4,%5,%6,%7},{%8,%9},{%0,%1,%2,%3};" \
                 : "+f"((d)[0]), "+f"((d)[1]), "+f"((d)[2]), "+f"((d)[3]) \
                 : "r"(a0), "r"(a1), "r"(a2), "r"(a3), "r"(b0), "r"(b1))

// ---------------------------------------------------------------------------
// bf16x3 GEMM: C[M,N] = (Ahi+Alo)[M,K] @ (Bhi+Blo)[N,K]^T + bias
// Shared tiling: BM=128, BN=128, KC=64; 4 tiles (Ahi,Alo,Bhi,Blo) x 16KB per stage.
// ---------------------------------------------------------------------------
#define KC 64
#define STAGE_BYTES 65536
#define NSTAGE 3
#define GEMM_SMEM (2048 + NSTAGE * STAGE_BYTES)

__device__ __forceinline__ void load_chunk_tiles(
    const __nv_bfloat16* __restrict__ Ah, const __nv_bfloat16* __restrict__ Al,
    const __nv_bfloat16* __restrict__ Bh, const __nv_bfloat16* __restrict__ Bl,
    int K, int m0, int n0, int c, uint32_t stBase, int tid)
{
    #pragma unroll
    for (int t = 0; t < 4; t++) {
        int idx = t * 256 + tid;
        int row = idx >> 3;
        int col = idx & 7;
        uint32_t off = SWZ128(row * 128 + col * 16);
        size_t ga = (size_t)(m0 + row) * K + c * KC + col * 8;
        size_t gb = (size_t)(n0 + row) * K + c * KC + col * 8;
        CP_ASYNC16(stBase + off,         Ah + ga);
        CP_ASYNC16(stBase + 16384 + off, Al + ga);
        CP_ASYNC16(stBase + 32768 + off, Bh + gb);
        CP_ASYNC16(stBase + 49152 + off, Bl + gb);
    }
}

__global__ __launch_bounds__(256, 1)
void gemm_bf16x3_kernel(const __nv_bfloat16* __restrict__ Ah,
                        const __nv_bfloat16* __restrict__ Al,
                        const __nv_bfloat16* __restrict__ Bh,
                        const __nv_bfloat16* __restrict__ Bl,
                        const float* __restrict__ bias,
                        float* __restrict__ C,
                        int N, int K)
{
    extern __shared__ char smem[];
    const uint32_t sb = smem_u32(smem);
    const uint32_t tiles = (sb + 1024 + 1023) & ~1023u;
    const int tid  = threadIdx.x;
    const int wid  = tid >> 5;
    const int lane = tid & 31;
    const int m0 = blockIdx.y * 128;
    const int n0 = blockIdx.x * 128;
    const int NCHUNK = K / KC;

#if USE_TCGEN05
    // ------------------ tcgen05 path (sm_103a cubin) ------------------
    if (wid == 0) {
        TCGEN05_ALLOC(sb, 128);
        TCGEN05_RELINQ();
    }
    if (tid == 0) {
        MBARRIER_INIT(sb + 8,  1);
        MBARRIER_INIT(sb + 16, 1);
        MBARRIER_INIT(sb + 24, 1);
    }
    __syncthreads();
    uint32_t tmem;
    asm volatile("ld.shared.b32 %0, [%1];" : "=r"(tmem) : "r"(sb));

    load_chunk_tiles(Ah, Al, Bh, Bl, K, m0, n0, 0, tiles + 0 * STAGE_BYTES, tid);
    CP_COMMIT();
    load_chunk_tiles(Ah, Al, Bh, Bl, K, m0, n0, 1, tiles + 1 * STAGE_BYTES, tid);
    CP_COMMIT();

    int ph0 = 0, ph1 = 0, ph2 = 0;

    for (int c = 0; c < NCHUNK; ++c) {
        const int s = c % NSTAGE;
        if (c >= NCHUNK - 2) { CP_WAIT0(); } else { CP_WAIT1(); }
        FENCE_PROXY_ASYNC();
        __syncthreads();

        if (tid == 0) {
            uint32_t st = tiles + s * STAGE_BYTES;
            uint64_t dAh = make_desc(st);
            uint64_t dAl = make_desc(st + 16384);
            uint64_t dBh = make_desc(st + 32768);
            uint64_t dBl = make_desc(st + 49152);
            #pragma unroll
            for (int k = 0; k < 4; k++) {
                mma_bf16_ss(tmem, dAh + k * 2, dBh + k * 2, IDESC_BF16_128x128,
                            (c == 0 && k == 0) ? 0u : 1u);
                mma_bf16_ss(tmem, dAh + k * 2, dBl + k * 2, IDESC_BF16_128x128, 1u);
                mma_bf16_ss(tmem, dAl + k * 2, dBh + k * 2, IDESC_BF16_128x128, 1u);
            }
            TCGEN05_COMMIT(sb + 8 + 8 * s);
        }

        const int n = c + 2;
        if (n < NCHUNK) {
            const int s2 = n % NSTAGE;
            if (n >= NSTAGE) {
                uint32_t mb = sb + 8 + 8 * s2;
                int& ph = (s2 == 0) ? ph0 : (s2 == 1) ? ph1 : ph2;
                MBARRIER_WAIT_PARITY(mb, (uint32_t)ph);
                ph ^= 1;
            }
            load_chunk_tiles(Ah, Al, Bh, Bl, K, m0, n0, n, tiles + s2 * STAGE_BYTES, tid);
            CP_COMMIT();
        }
    }

    {
        const int sl = (NCHUNK - 1) % NSTAGE;
        uint32_t mb = sb + 8 + 8 * sl;
        int& ph = (sl == 0) ? ph0 : (sl == 1) ? ph1 : ph2;
        MBARRIER_WAIT_PARITY(mb, (uint32_t)ph);
        ph ^= 1;
    }
    TCGEN05_FENCE_AFTER();

    if (wid < 4) {
        const int mrow = wid * 32 + lane;
        float* crow = C + (size_t)(m0 + mrow) * N + n0;
        #pragma unroll
        for (int cb = 0; cb < 128; cb += 32) {
            uint32_t r[32];
            LDTM_X32(r, tmem + cb);
            TCGEN05_WAIT_LD();
            #pragma unroll
            for (int j = 0; j < 32; j += 4) {
                float4 bv = *(const float4*)(bias + n0 + cb + j);
                float4 o;
                o.x = __uint_as_float(r[j + 0]) + bv.x;
                o.y = __uint_as_float(r[j + 1]) + bv.y;
                o.z = __uint_as_float(r[j + 2]) + bv.z;
                o.w = __uint_as_float(r[j + 3]) + bv.w;
                *(float4*)(crow + cb + j) = o;
            }
        }
        TCGEN05_FENCE_BEFORE();
    }

    __syncthreads();
    if (wid == 0) {
        TCGEN05_DEALLOC(tmem, 128);
    }
#else
    // ------------------ mma.sync fallback path (plain sm_103) ------------------
    const int warpM = wid >> 2;        // 0..1
    const int warpN = wid & 3;         // 0..3

    float acc[4][4][4];
    #pragma unroll
    for (int mt = 0; mt < 4; mt++)
        #pragma unroll
        for (int nt = 0; nt < 4; nt++)
            #pragma unroll
            for (int e = 0; e < 4; e++) acc[mt][nt][e] = 0.0f;

    // per-lane ldmatrix address components
    const int aRowBase  = warpM * 64 + (lane & 15);
    const int aByteSel  = (lane >> 4) * 16;
    const int bRowBase  = warpN * 32 + (lane & 7);
    const int bByteSel  = ((lane >> 3) & 1) * 16;

    load_chunk_tiles(Ah, Al, Bh, Bl, K, m0, n0, 0, tiles, tid);
    CP_COMMIT();

    for (int c = 0; c < NCHUNK; ++c) {
        if (c + 1 < NCHUNK) {
            load_chunk_tiles(Ah, Al, Bh, Bl, K, m0, n0, c + 1,
                             tiles + ((c + 1) & 1) * STAGE_BYTES, tid);
            CP_COMMIT();
            CP_WAIT1();
        } else {
            CP_WAIT0();
        }
        __syncthreads();

        const uint32_t st  = tiles + (c & 1) * STAGE_BYTES;
        const uint32_t aHi = st;
        const uint32_t aLo = st + 16384;
        const uint32_t bHi = st + 32768;
        const uint32_t bLo = st + 49152;

        #pragma unroll
        for (int kk = 0; kk < 4; kk++) {
            uint32_t bh[4][2], bl[4][2];
            #pragma unroll
            for (int nt = 0; nt < 4; nt++) {
                uint32_t boff = SWZ128((uint32_t)((bRowBase + nt * 8) * 128 + kk * 32 + bByteSel));
                LDSM_X2(bh[nt][0], bh[nt][1], bHi + boff);
                LDSM_X2(bl[nt][0], bl[nt][1], bLo + boff);
            }
            #pragma unroll
            for (int mt = 0; mt < 4; mt++) {
                uint32_t aoff = SWZ128((uint32_t)((aRowBase + mt * 16) * 128 + kk * 32 + aByteSel));
                uint32_t ah0, ah1, ah2, ah3, al0, al1, al2, al3;
                LDSM_X4(ah0, ah1, ah2, ah3, aHi + aoff);
                LDSM_X4(al0, al1, al2, al3, aLo + aoff);
                #pragma unroll
                for (int nt = 0; nt < 4; nt++) {
                    MMA16816(acc[mt][nt], ah0, ah1, ah2, ah3, bh[nt][0], bh[nt][1]);
                    MMA16816(acc[mt][nt], al0, al1, al2, al3, bh[nt][0], bh[nt][1]);
                    MMA16816(acc[mt][nt], ah0, ah1, ah2, ah3, bl[nt][0], bl[nt][1]);
                }
            }
        }
        __syncthreads();
    }

    // epilogue: bias + store (float2 per acc half)
    #pragma unroll
    for (int mt = 0; mt < 4; mt++) {
        int r0 = m0 + warpM * 64 + mt * 16 + (lane >> 2);
        #pragma unroll
        for (int nt = 0; nt < 4; nt++) {
            int c0 = n0 + warpN * 32 + nt * 8 + (lane & 3) * 2;
            float2 bv = *(const float2*)(bias + c0);
            float2 o0 = make_float2(acc[mt][nt][0] + bv.x, acc[mt][nt][1] + bv.y);
            float2 o1 = make_float2(acc[mt][nt][2] + bv.x, acc[mt][nt][3] + bv.y);
            *(float2*)(C + (size_t)r0 * N + c0)       = o0;
            *(float2*)(C + (size_t)(r0 + 8) * N + c0) = o1;
        }
    }
#endif
}

// ---------------------------------------------------------------------------
// Split fp32 -> bf16 hi + bf16 residual lo
// ---------------------------------------------------------------------------
__global__ __launch_bounds__(256)
void conv_split_kernel(const float* __restrict__ in,
                       __nv_bfloat16* __restrict__ hi,
                       __nv_bfloat16* __restrict__ lo, int n4)
{
    int i = blockIdx.x * 256 + threadIdx.x;
    if (i >= n4) return;
    float4 v = ((const float4*)in)[i];
    __nv_bfloat16 h0 = __float2bfloat16(v.x);
    __nv_bfloat16 h1 = __float2bfloat16(v.y);
    __nv_bfloat16 h2 = __float2bfloat16(v.z);
    __nv_bfloat16 h3 = __float2bfloat16(v.w);
    __nv_bfloat16 l0 = __float2bfloat16(v.x - __bfloat162float(h0));
    __nv_bfloat16 l1 = __float2bfloat16(v.y - __bfloat162float(h1));
    __nv_bfloat16 l2 = __float2bfloat16(v.z - __bfloat162float(h2));
    __nv_bfloat16 l3 = __float2bfloat16(v.w - __bfloat162float(h3));
    ((__nv_bfloat162*)hi)[2 * i + 0] = __nv_bfloat162(h0, h1);
    ((__nv_bfloat162*)hi)[2 * i + 1] = __nv_bfloat162(h2, h3);
    ((__nv_bfloat162*)lo)[2 * i + 0] = __nv_bfloat162(l0, l1);
    ((__nv_bfloat162*)lo)[2 * i + 1] = __nv_bfloat162(l2, l3);
}

// ---------------------------------------------------------------------------
// Transpose + split: W[K,N] fp32 -> Wt hi/lo [N,K] bf16
// ---------------------------------------------------------------------------
__global__ __launch_bounds__(256)
void conv_transpose_kernel(const float* __restrict__ W,
                           __nv_bfloat16* __restrict__ hi,
                           __nv_bfloat16* __restrict__ lo, int K, int N)
{
    __shared__ float tile[32][33];
    const int n0 = blockIdx.x * 32;
    const int k0 = blockIdx.y * 32;
    const int tx = threadIdx.x & 31;
    const int ty = threadIdx.x >> 5;

    #pragma unroll
    for (int j = ty; j < 32; j += 8)
        tile[j][tx] = W[(size_t)(k0 + j) * N + n0 + tx];
    __syncthreads();

    #pragma unroll
    for (int j = ty; j < 32; j += 8) {
        float v = tile[tx][j];
        __nv_bfloat16 h = __float2bfloat16(v);
        __nv_bfloat16 l = __float2bfloat16(v - __bfloat162float(h));
        size_t o = (size_t)(n0 + j) * K + k0 + tx;
        hi[o] = h;
        lo[o] = l;
    }
}

// ---------------------------------------------------------------------------
// Fenwick sparse attention: <=12 keys per query, one warp per (b,h,t)
// ---------------------------------------------------------------------------
__global__ __launch_bounds__(256)
void fenwick_attn_kernel(const float* __restrict__ qkv, float* __restrict__ out)
{
    const int warp = threadIdx.x >> 5;
    const int lane = threadIdx.x & 31;
    const int t  = blockIdx.x * 8 + warp;
    const int bh = blockIdx.y;
    const int b = bh >> 4;
    const int h = bh & 15;

    const float scale = 0.125f;
    const size_t rowStride = 3 * CH;
    const float* base = qkv + (size_t)b * SEQ * rowStride;

    const float* qp = base + (size_t)t * rowStride + h * DH;
    const float q0 = qp[lane];
    const float q1 = qp[lane + 32];

    int pos[12];
    int np = 0;
    pos[np++] = t;
    for (int step = 1; t - step >= 0; step <<= 1) pos[np++] = t - step;

    float s[12];
    float m = -CUDART_INF_F;
    for (int i = 0; i < np; i++) {
        const float* kp = base + (size_t)pos[i] * rowStride + CH + h * DH;
        float d = q0 * kp[lane] + q1 * kp[lane + 32];
        #pragma unroll
        for (int off = 16; off; off >>= 1) d += __shfl_xor_sync(0xFFFFFFFFu, d, off);
        d *= scale;
        s[i] = d;
        m = fmaxf(m, d);
    }

    float denom = 0.0f;
    for (int i = 0; i < np; i++) { s[i] = __expf(s[i] - m); denom += s[i]; }
    const float inv = 1.0f / denom;

    float o0 = 0.0f, o1 = 0.0f;
    for (int i = 0; i < np; i++) {
        const float* vp = base + (size_t)pos[i] * rowStride + 2 * CH + h * DH;
        o0 = fmaf(s[i], vp[lane], o0);
        o1 = fmaf(s[i], vp[lane + 32], o1);
    }

    float* op = out + ((size_t)b * SEQ + t) * CH + h * DH;
    op[lane]      = o0 * inv;
    op[lane + 32] = o1 * inv;
}

// ---------------------------------------------------------------------------
// Launch
// ---------------------------------------------------------------------------
extern "C" void kernel_launch(void* const* d_in, const int* in_sizes, int n_in,
                              void* d_out, int out_size)
{
    const float* x      = (const float*)d_in[0];
    const float* W_qkv  = (const float*)d_in[1];
    const float* b_qkv  = (const float*)d_in[2];
    const float* W_proj = (const float*)d_in[3];
    const float* b_proj = (const float*)d_in[4];
    float* out = (float*)d_out;

    float *qkv, *att;
    __nv_bfloat16 *Ahi, *Alo, *BQhi, *BQlo, *BPhi, *BPlo;
    cudaGetSymbolAddress((void**)&qkv,  g_qkv);
    cudaGetSymbolAddress((void**)&att,  g_att);
    cudaGetSymbolAddress((void**)&Ahi,  g_Ahi);
    cudaGetSymbolAddress((void**)&Alo,  g_Alo);
    cudaGetSymbolAddress((void**)&BQhi, g_BQhi);
    cudaGetSymbolAddress((void**)&BQlo, g_BQlo);
    cudaGetSymbolAddress((void**)&BPhi, g_BPhi);
    cudaGetSymbolAddress((void**)&BPlo, g_BPlo);

    cudaFuncSetAttribute(gemm_bf16x3_kernel,
                         cudaFuncAttributeMaxDynamicSharedMemorySize, GEMM_SMEM);

    conv_transpose_kernel<<<dim3(3 * CH / 32, CH / 32), 256>>>(W_qkv, BQhi, BQlo, CH, 3 * CH);
    conv_transpose_kernel<<<dim3(CH / 32, CH / 32), 256>>>(W_proj, BPhi, BPlo, CH, CH);
    conv_split_kernel<<<(MROWS * CH / 4 + 255) / 256, 256>>>(x, Ahi, Alo, MROWS * CH / 4);

    gemm_bf16x3_kernel<<<dim3(3 * CH / 128, MROWS / 128), 256, GEMM_SMEM>>>(
        Ahi, Alo, BQhi, BQlo, b_qkv, qkv, 3 * CH, CH);

    fenwick_attn_kernel<<<dim3(SEQ / 8, BATCH * HEADS), 256>>>(qkv, att);

    conv_split_kernel<<<(MROWS * CH / 4 + 255) / 256, 256>>>(att, Ahi, Alo, MROWS * CH / 4);

    gemm_bf16x3_kernel<<<dim3(CH / 128, MROWS / 128), 256, GEMM_SMEM>>>(
        Ahi, Alo, BPhi, BPlo, b_proj, out, CH, CH);
}